// round 14
// baseline (speedup 1.0000x reference)
#include <cuda_runtime.h>

// Depthwise separable FIR [1,3,3,1]x[1,3,3,1]/64, pad 1,
// in: [16,256,128,128] f32 -> out: [16,256,127,127] f32
//
// Warp = 32-output-row band of one plane. Horizontal pass via register
// shuffles (warp edges == zero padding), vertical pass via running
// accumulators. Output stores are realigned IN REGISTERS to 16B phase:
// row start phase s = (yo - plane) & 3 is uniform per warp and cycles with
// period 4, so with S0 templating + 4x unroll every shift is compile-time.
// Per row: 31 aligned STG.128 (lanes 0..30) + 3 scalar head/tail floats.
// No shared memory at all.

#define H_IN   128
#define W_IN   128
#define H_OUT  127
#define W_OUT  127
#define NTHREADS 128          // 4 warps = 4 bands = one plane per block

__device__ __forceinline__ float4 fir_h(const float4 v, const int lane) {
    const unsigned FULL = 0xffffffffu;
    float lw = __shfl_up_sync(FULL, v.w, 1);
    float r1 = __shfl_down_sync(FULL, v.x, 1);
    float r2 = __shfl_down_sync(FULL, v.y, 1);
    if (lane == 0)  lw = 0.f;
    if (lane == 31) { r1 = 0.f; r2 = 0.f; }
    float4 h;
    h.x = lw  + 3.f * (v.x + v.y) + v.z;
    h.y = v.x + 3.f * (v.y + v.z) + v.w;
    h.z = v.y + 3.f * (v.z + v.w) + r1;
    h.w = v.z + 3.f * (v.w + r1)  + r2;
    return h;
}

__device__ __forceinline__ void acc_advance(float4& a0, float4& a1, float4& a2,
                                            const float4 h) {
    const float tx = 3.f * h.x, ty = 3.f * h.y, tz = 3.f * h.z, tw = 3.f * h.w;
    a0.x = a1.x + tx; a0.y = a1.y + ty; a0.z = a1.z + tz; a0.w = a1.w + tw;
    a1.x = a2.x + tx; a1.y = a2.y + ty; a1.z = a2.z + tz; a1.w = a2.w + tw;
    a2 = h;
}

// One output row. S = (yo - plane) & 3, compile-time.
template<int S>
__device__ __forceinline__ void row_iter(const float* __restrict__ xp,
                                         float* __restrict__ opBase,
                                         const int y0, const int r,
                                         const int lane,
                                         float4& a0, float4& a1, float4& a2) {
    const unsigned FULL = 0xffffffffu;
    const int yo = y0 + r;
    const int j  = yo + 2;                          // new h-row
    const int jc = j > H_IN - 1 ? H_IN - 1 : j;
    const float4 v = __ldg((const float4*)(xp + (size_t)jc * W_IN));
    float4 h = fir_h(v, lane);
    if (j >= H_IN) { h.x = 0.f; h.y = 0.f; h.z = 0.f; h.w = 0.f; }

    float4 o;
    o.x = (a0.x + h.x) * (1.f / 64.f);
    o.y = (a0.y + h.y) * (1.f / 64.f);
    o.z = (a0.z + h.z) * (1.f / 64.f);
    o.w = (a0.w + h.w) * (1.f / 64.f);

    if (yo < H_OUT) {                               // uniform predicate
        // neighbor's o for the sliding window
        float4 n;
        n.x = __shfl_down_sync(FULL, o.x, 1);
        n.y = __shfl_down_sync(FULL, o.y, 1);
        n.z = __shfl_down_sync(FULL, o.z, 1);
        // window: lane l holds row elements [S+4l, S+4l+4)
        float4 w;
        if (S == 0)      { w.x = o.x; w.y = o.y; w.z = o.z; w.w = o.w; }
        else if (S == 1) { w.x = o.y; w.y = o.z; w.z = o.w; w.w = n.x; }
        else if (S == 2) { w.x = o.z; w.y = o.w; w.z = n.x; w.w = n.y; }
        else             { w.x = o.w; w.y = n.x; w.z = n.y; w.w = n.z; }

        float* g = opBase + (size_t)yo * W_OUT;     // row start (phase-aligned at +S)
        if (lane < 31)
            *(float4*)(g + S + 4 * lane) = w;       // elements S .. S+123
        // head: elements 0..S-1 live in lane 0's o
        if (S > 0 && lane == 0) {
            g[0] = o.x;
            if (S > 1) g[1] = o.y;
            if (S > 2) g[2] = o.z;
        }
        // tail: elements S+124..126 live in lane 31's o
        if (S < 3 && lane == 31) {
            if (S == 0) { g[124] = o.x; g[125] = o.y; g[126] = o.z; }
            else if (S == 1) { g[125] = o.y; g[126] = o.z; }
            else { g[126] = o.z; }
        }
    }
    acc_advance(a0, a1, a2, h);
}

template<int S0>
__device__ __forceinline__ void band(const float* __restrict__ xp,
                                     float* __restrict__ opBase,
                                     const int y0, const int lane) {
    float4 a0 = make_float4(0.f, 0.f, 0.f, 0.f);
    float4 a1 = a0, a2 = a0;

    // prologue: h-rows y0-1 .. y0+1
    #pragma unroll
    for (int pj = 0; pj < 3; ++pj) {
        const int j  = y0 - 1 + pj;
        const int jc = j < 0 ? 0 : j;               // j <= 97 here, no upper clamp
        const float4 v = __ldg((const float4*)(xp + (size_t)jc * W_IN));
        float4 h = fir_h(v, lane);
        if (j < 0) { h.x = 0.f; h.y = 0.f; h.z = 0.f; h.w = 0.f; }
        acc_advance(a0, a1, a2, h);
    }

    // 32 output rows; phase cycles with period 4 -> compile-time S per body
    #pragma unroll 2
    for (int ro = 0; ro < 8; ++ro) {
        const int rb = ro * 4;
        row_iter<(S0 + 0) & 3>(xp, opBase, y0, rb + 0, lane, a0, a1, a2);
        row_iter<(S0 + 1) & 3>(xp, opBase, y0, rb + 1, lane, a0, a1, a2);
        row_iter<(S0 + 2) & 3>(xp, opBase, y0, rb + 2, lane, a0, a1, a2);
        row_iter<(S0 + 3) & 3>(xp, opBase, y0, rb + 3, lane, a0, a1, a2);
    }
}

__global__ __launch_bounds__(NTHREADS)
void fir4x4_regalign_kernel(const float* __restrict__ x, float* __restrict__ out) {
    const int lane  = threadIdx.x & 31;
    const int wid   = threadIdx.x >> 5;
    const int plane = blockIdx.x;                   // 0..4095
    const int y0    = wid * 32;

    const float* xp = x   + (size_t)plane * (H_IN * W_IN) + lane * 4;
    float* opBase   = out + (size_t)plane * (H_OUT * W_OUT);

    // S for row yo: (yo - plane) & 3; y0 % 4 == 0, so band-start S0 = (-plane)&3
    switch (plane & 3) {
        case 0: band<0>(xp, opBase, y0, lane); break;
        case 1: band<3>(xp, opBase, y0, lane); break;
        case 2: band<2>(xp, opBase, y0, lane); break;
        default: band<1>(xp, opBase, y0, lane); break;
    }
}

extern "C" void kernel_launch(void* const* d_in, const int* in_sizes, int n_in,
                              void* d_out, int out_size) {
    const float* x = (const float*)d_in[0];
    float* out = (float*)d_out;
    fir4x4_regalign_kernel<<<16 * 256, NTHREADS>>>(x, out);
}